// round 1
// baseline (speedup 1.0000x reference)
#include <cuda_runtime.h>
#include <cuda_bf16.h>
#include <math.h>

// Problem constants (fixed by the dataset instance)
#define B_   64
#define E_   1280
#define H_   20
#define D_   64
#define NB_  7
#define BS_  64
#define L_   (NB_*BS_)      // 448
#define SCALING 0.125f      // 64^-0.5

// Scratch (device globals: allocation-free)
__device__ float g_q[B_ * E_];
__device__ float g_k[B_ * E_];
__device__ float g_v[B_ * E_];
__device__ float g_attn[B_ * E_];

// ---------------------------------------------------------------------------
// Init: write biases into q/k/v accumulators and bo into d_out
// ---------------------------------------------------------------------------
__global__ void init_kernel(const float* __restrict__ bq, const float* __restrict__ bk,
                            const float* __restrict__ bv, const float* __restrict__ bo,
                            float* __restrict__ out) {
    int i = blockIdx.x * blockDim.x + threadIdx.x;   // 0 .. B*E-1
    if (i < B_ * E_) {
        int j = i % E_;
        g_q[i] = bq[j];
        g_k[i] = bk[j];
        g_v[i] = bv[j];
        out[i] = bo[j];
    }
}

// ---------------------------------------------------------------------------
// GEMM: out[b][j] += sum_k A[b][k] * W[j][k]   (A: [64,1280], W: [1280,1280])
// Tile: M=64 (all rows) x N=32, K-chunk per blockIdx.y (split-K, atomicAdd).
// 256 threads, 4x2 micro-tile per thread.
// src_sel: 0..2 -> A = hidden param, out = g_q/g_k/g_v
//          3    -> A = g_attn,       out = out_param (d_out)
// ---------------------------------------------------------------------------
#define TN 32
#define TK 32

__global__ void gemm_kernel(const float* __restrict__ A_param,
                            const float* __restrict__ W,
                            float* __restrict__ out_param,
                            int src_sel, int KC) {
    __shared__ float As[TK][72];   // [k][m], row stride 72 (16B-aligned rows)
    __shared__ float Bs[TK][36];   // [k][n], row stride 36 (8B-aligned rows)

    const float* A;
    float* out;
    if (src_sel == 0)      { A = A_param; out = g_q; }
    else if (src_sel == 1) { A = A_param; out = g_k; }
    else if (src_sel == 2) { A = A_param; out = g_v; }
    else                   { A = g_attn;  out = out_param; }

    const int j0 = blockIdx.x * TN;
    const int k0 = blockIdx.y * KC;
    const int t  = threadIdx.x;

    float acc[4][2] = {};
    const int tm = (t & 15) * 4;     // 0..60
    const int tn = (t >> 4) * 2;     // 0..30

    for (int kt = k0; kt < k0 + KC; kt += TK) {
        // Load A tile: 64 rows x 32 k  (512 float4s / 256 threads = 2 each)
        #pragma unroll
        for (int r = 0; r < 2; r++) {
            int f  = t + r * 256;             // 0..511
            int b  = f >> 3;
            int kc = f & 7;
            float4 v = *(const float4*)(A + b * E_ + kt + kc * 4);
            As[kc * 4 + 0][b] = v.x;
            As[kc * 4 + 1][b] = v.y;
            As[kc * 4 + 2][b] = v.z;
            As[kc * 4 + 3][b] = v.w;
        }
        // Load W tile: 32 rows (j) x 32 k (256 float4s / 256 threads)
        {
            int j  = t >> 3;
            int kc = t & 7;
            float4 v = *(const float4*)(W + (size_t)(j0 + j) * E_ + kt + kc * 4);
            Bs[kc * 4 + 0][j] = v.x;
            Bs[kc * 4 + 1][j] = v.y;
            Bs[kc * 4 + 2][j] = v.z;
            Bs[kc * 4 + 3][j] = v.w;
        }
        __syncthreads();

        #pragma unroll
        for (int k = 0; k < TK; k++) {
            float4 a  = *(const float4*)&As[k][tm];
            float2 bb = *(const float2*)&Bs[k][tn];
            acc[0][0] += a.x * bb.x;  acc[0][1] += a.x * bb.y;
            acc[1][0] += a.y * bb.x;  acc[1][1] += a.y * bb.y;
            acc[2][0] += a.z * bb.x;  acc[2][1] += a.z * bb.y;
            acc[3][0] += a.w * bb.x;  acc[3][1] += a.w * bb.y;
        }
        __syncthreads();
    }

    #pragma unroll
    for (int i = 0; i < 4; i++)
        #pragma unroll
        for (int j = 0; j < 2; j++)
            atomicAdd(&out[(tm + i) * E_ + j0 + tn + j], acc[i][j]);
}

// ---------------------------------------------------------------------------
// Attention: one CTA per (b, h). 256 threads.
//   scores: warp-per-row coalesced dot over D=64
//   softmax: block reduce
//   P*V: 4 l-partitions x 64 d
// ---------------------------------------------------------------------------
__global__ void attn_kernel(const float* __restrict__ kcache,
                            const float* __restrict__ vcache,
                            const int* __restrict__ cache_position,
                            const int* __restrict__ block_tables) {
    __shared__ float qs[D_];
    __shared__ float sc[L_];
    __shared__ float redbuf[8];
    __shared__ float red2[8];
    __shared__ int   bts[NB_];
    __shared__ float pvb[4][D_];

    const int b = blockIdx.x;
    const int h = blockIdx.y;
    const int tid  = threadIdx.x;
    const int warp = tid >> 5;
    const int lane = tid & 31;

    if (tid < D_)  qs[tid]  = g_q[b * E_ + h * D_ + tid];
    if (tid < NB_) bts[tid] = block_tables[b * NB_ + tid];
    const int pos = cache_position[b];
    const int n   = pos + 1;
    __syncthreads();

    const size_t bh_base = ((size_t)b * H_ + h) * NB_;   // * BS_*D_ later
    const float* knew = &g_k[b * E_ + h * D_];
    const float* vnew = &g_v[b * E_ + h * D_];

    // ---- scores ----
    for (int l = warp; l < n; l += 8) {
        const float* kr;
        if (l == pos) {
            kr = knew;
        } else {
            int blk = bts[l >> 6];
            kr = kcache + ((bh_base + blk) * BS_ + (l & 63)) * D_;
        }
        float2 kv = ((const float2*)kr)[lane];
        float p = qs[2 * lane] * kv.x + qs[2 * lane + 1] * kv.y;
        #pragma unroll
        for (int o = 16; o > 0; o >>= 1)
            p += __shfl_xor_sync(0xFFFFFFFFu, p, o);
        if (lane == 0) sc[l] = p * SCALING;
    }
    __syncthreads();

    // ---- softmax: max ----
    float m = -1e30f;
    for (int l = tid; l < n; l += 256) m = fmaxf(m, sc[l]);
    #pragma unroll
    for (int o = 16; o > 0; o >>= 1)
        m = fmaxf(m, __shfl_xor_sync(0xFFFFFFFFu, m, o));
    if (lane == 0) redbuf[warp] = m;
    __syncthreads();
    if (warp == 0) {
        float x = (lane < 8) ? redbuf[lane] : -1e30f;
        #pragma unroll
        for (int o = 4; o > 0; o >>= 1)
            x = fmaxf(x, __shfl_xor_sync(0xFFFFFFFFu, x, o));
        if (lane == 0) redbuf[0] = x;
    }
    __syncthreads();
    m = redbuf[0];

    // ---- exp + sum ----
    float s = 0.f;
    for (int l = tid; l < n; l += 256) {
        float e = __expf(sc[l] - m);
        sc[l] = e;
        s += e;
    }
    #pragma unroll
    for (int o = 16; o > 0; o >>= 1)
        s += __shfl_xor_sync(0xFFFFFFFFu, s, o);
    if (lane == 0) red2[warp] = s;
    __syncthreads();
    if (warp == 0) {
        float x = (lane < 8) ? red2[lane] : 0.f;
        #pragma unroll
        for (int o = 4; o > 0; o >>= 1)
            x += __shfl_xor_sync(0xFFFFFFFFu, x, o);
        if (lane == 0) red2[0] = x;
    }
    __syncthreads();
    const float inv = 1.0f / red2[0];

    // ---- P * V ----
    const int d    = tid & 63;
    const int part = tid >> 6;   // 0..3
    float acc = 0.f;
    for (int l = part; l < n; l += 4) {
        const float* vr;
        if (l == pos) {
            vr = vnew;
        } else {
            int blk = bts[l >> 6];
            vr = vcache + ((bh_base + blk) * BS_ + (l & 63)) * D_;
        }
        acc += sc[l] * vr[d];
    }
    pvb[part][d] = acc;
    __syncthreads();
    if (tid < D_) {
        float o = (pvb[0][tid] + pvb[1][tid]) + (pvb[2][tid] + pvb[3][tid]);
        g_attn[b * E_ + h * D_ + tid] = o * inv;
    }
}

// ---------------------------------------------------------------------------
extern "C" void kernel_launch(void* const* d_in, const int* in_sizes, int n_in,
                              void* d_out, int out_size) {
    const float* hidden = (const float*)d_in[0];
    const float* kcache = (const float*)d_in[1];
    const float* vcache = (const float*)d_in[2];
    const float* wq     = (const float*)d_in[3];
    const float* bq     = (const float*)d_in[4];
    const float* wk     = (const float*)d_in[5];
    const float* bk     = (const float*)d_in[6];
    const float* wv     = (const float*)d_in[7];
    const float* bv     = (const float*)d_in[8];
    const float* wo     = (const float*)d_in[9];
    const float* bo     = (const float*)d_in[10];
    const int*   cpos   = (const int*)d_in[11];
    const int*   btab   = (const int*)d_in[12];
    float* out = (float*)d_out;

    init_kernel<<<(B_ * E_ + 255) / 256, 256>>>(bq, bk, bv, bo, out);

    // QKV projections: split-K x2 -> 240 blocks total
    gemm_kernel<<<dim3(E_ / TN, 2), 256>>>(hidden, wq, nullptr, 0, E_ / 2);
    gemm_kernel<<<dim3(E_ / TN, 2), 256>>>(hidden, wk, nullptr, 1, E_ / 2);
    gemm_kernel<<<dim3(E_ / TN, 2), 256>>>(hidden, wv, nullptr, 2, E_ / 2);

    attn_kernel<<<dim3(B_, H_), 256>>>(kcache, vcache, cpos, btab);

    // Output projection: split-K x4 -> 160 blocks
    gemm_kernel<<<dim3(E_ / TN, 4), 256>>>(nullptr, wo, out, 3, E_ / 4);
}

// round 2
// speedup vs baseline: 1.7716x; 1.7716x over previous
#include <cuda_runtime.h>
#include <cuda_bf16.h>
#include <math.h>

// Problem constants
#define B_   64
#define E_   1280
#define H_   20
#define D_   64
#define NB_  7
#define BS_  64
#define L_   (NB_*BS_)      // 448
#define SCALING 0.125f      // 64^-0.5

// Scratch (device globals: allocation-free)
__device__ float g_q[B_ * E_];
__device__ float g_k[B_ * E_];
__device__ float g_v[B_ * E_];
__device__ float g_attn[B_ * E_];

// ---------------------------------------------------------------------------
// Init: biases into q/k/v accumulators and bo into d_out
// ---------------------------------------------------------------------------
__global__ void init_kernel(const float* __restrict__ bq, const float* __restrict__ bk,
                            const float* __restrict__ bv, const float* __restrict__ bo,
                            float* __restrict__ out) {
    int i = blockIdx.x * blockDim.x + threadIdx.x;
    if (i < B_ * E_) {
        int j = i % E_;
        g_q[i] = bq[j];
        g_k[i] = bk[j];
        g_v[i] = bv[j];
        out[i] = bo[j];
    }
}

// ---------------------------------------------------------------------------
// GEMM core: C[64, Ntile=128] += A[64, K] * W[N, K]^T over k in [k0, k0+KC)
// 256 threads. Per-thread micro-tile: 8 m (4+4 split, stride 32) x 4 n.
// Results accumulated into out via atomicAdd (bias pre-loaded by init).
// ---------------------------------------------------------------------------
#define GTN 128
#define GTK 16

__device__ __forceinline__ void gemm_core(const float* __restrict__ A,
                                          const float* __restrict__ W,
                                          float* __restrict__ out,
                                          int j0, int k0, int KC) {
    __shared__ float As[GTK][72];    // [k][m], stride 72 (288B, 16B-aligned)
    __shared__ float Ws[GTK][132];   // [k][n], stride 132 (528B, 16B-aligned)

    const int t = threadIdx.x;
    const int m0 = (t & 7) * 4;       // rows m0..m0+3 and m0+32..m0+35
    const int tn = (t >> 3) * 4;      // cols tn..tn+3 (0..124)

    float acc[8][4] = {};

    const int arow = t >> 2;          // A loader: row 0..63
    const int akq  = t & 3;           // k-quad 0..3

    for (int kt = k0; kt < k0 + KC; kt += GTK) {
        // A tile: 64 x 16 (256 float4s)
        {
            float4 v = *(const float4*)(A + arow * E_ + kt + akq * 4);
            As[akq * 4 + 0][arow] = v.x;
            As[akq * 4 + 1][arow] = v.y;
            As[akq * 4 + 2][arow] = v.z;
            As[akq * 4 + 3][arow] = v.w;
        }
        // W tile: 128 x 16 (512 float4s)
        #pragma unroll
        for (int r = 0; r < 2; r++) {
            int f  = t + r * 256;
            int j  = f >> 2;
            int kq = f & 3;
            float4 v = *(const float4*)(W + (size_t)(j0 + j) * E_ + kt + kq * 4);
            Ws[kq * 4 + 0][j] = v.x;
            Ws[kq * 4 + 1][j] = v.y;
            Ws[kq * 4 + 2][j] = v.z;
            Ws[kq * 4 + 3][j] = v.w;
        }
        __syncthreads();

        #pragma unroll
        for (int k = 0; k < GTK; k++) {
            float4 a0 = *(const float4*)&As[k][m0];
            float4 a1 = *(const float4*)&As[k][m0 + 32];
            float4 w  = *(const float4*)&Ws[k][tn];
            float am[8] = {a0.x, a0.y, a0.z, a0.w, a1.x, a1.y, a1.z, a1.w};
            float wn[4] = {w.x, w.y, w.z, w.w};
            #pragma unroll
            for (int i = 0; i < 8; i++)
                #pragma unroll
                for (int j = 0; j < 4; j++)
                    acc[i][j] += am[i] * wn[j];
        }
        __syncthreads();
    }

    #pragma unroll
    for (int i = 0; i < 8; i++) {
        int m = (i < 4) ? (m0 + i) : (m0 + 32 + (i - 4));
        #pragma unroll
        for (int j = 0; j < 4; j++)
            atomicAdd(&out[m * E_ + j0 + tn + j], acc[i][j]);
    }
}

// QKV fused: grid (10 n-tiles, 5 k-splits, 3 weights), KC=256
__global__ void qkv_kernel(const float* __restrict__ hidden,
                           const float* __restrict__ wq,
                           const float* __restrict__ wk,
                           const float* __restrict__ wv) {
    const float* W;
    float* out;
    if (blockIdx.z == 0)      { W = wq; out = g_q; }
    else if (blockIdx.z == 1) { W = wk; out = g_k; }
    else                      { W = wv; out = g_v; }
    gemm_core(hidden, W, out, blockIdx.x * GTN, blockIdx.y * 256, 256);
}

// O-proj: grid (10 n-tiles, 10 k-splits), KC=128
__global__ void oproj_kernel(const float* __restrict__ wo, float* __restrict__ out) {
    gemm_core(g_attn, wo, out, blockIdx.x * GTN, blockIdx.y * 128, 128);
}

// ---------------------------------------------------------------------------
// Attention: one CTA per (b, h). 256 threads.
// ---------------------------------------------------------------------------
__global__ void attn_kernel(const float* __restrict__ kcache,
                            const float* __restrict__ vcache,
                            const int* __restrict__ cache_position,
                            const int* __restrict__ block_tables) {
    __shared__ float qs[D_];
    __shared__ float sc[L_];
    __shared__ float redbuf[8];
    __shared__ float red2[8];
    __shared__ int   bts[NB_];
    __shared__ float pvb[4][D_];

    const int b = blockIdx.x;
    const int h = blockIdx.y;
    const int tid  = threadIdx.x;
    const int warp = tid >> 5;
    const int lane = tid & 31;

    if (tid < D_)  qs[tid]  = g_q[b * E_ + h * D_ + tid];
    if (tid < NB_) bts[tid] = block_tables[b * NB_ + tid];
    const int pos = cache_position[b];
    const int n   = pos + 1;
    __syncthreads();

    const size_t bh_base = ((size_t)b * H_ + h) * NB_;
    const float* knew = &g_k[b * E_ + h * D_];
    const float* vnew = &g_v[b * E_ + h * D_];

    // ---- scores ----
    for (int l = warp; l < n; l += 8) {
        const float* kr;
        if (l == pos) {
            kr = knew;
        } else {
            int blk = bts[l >> 6];
            kr = kcache + ((bh_base + blk) * BS_ + (l & 63)) * D_;
        }
        float2 kv = ((const float2*)kr)[lane];
        float p = qs[2 * lane] * kv.x + qs[2 * lane + 1] * kv.y;
        #pragma unroll
        for (int o = 16; o > 0; o >>= 1)
            p += __shfl_xor_sync(0xFFFFFFFFu, p, o);
        if (lane == 0) sc[l] = p * SCALING;
    }
    __syncthreads();

    // ---- softmax: max ----
    float m = -1e30f;
    for (int l = tid; l < n; l += 256) m = fmaxf(m, sc[l]);
    #pragma unroll
    for (int o = 16; o > 0; o >>= 1)
        m = fmaxf(m, __shfl_xor_sync(0xFFFFFFFFu, m, o));
    if (lane == 0) redbuf[warp] = m;
    __syncthreads();
    if (warp == 0) {
        float x = (lane < 8) ? redbuf[lane] : -1e30f;
        #pragma unroll
        for (int o = 4; o > 0; o >>= 1)
            x = fmaxf(x, __shfl_xor_sync(0xFFFFFFFFu, x, o));
        if (lane == 0) redbuf[0] = x;
    }
    __syncthreads();
    m = redbuf[0];

    // ---- exp + sum ----
    float s = 0.f;
    for (int l = tid; l < n; l += 256) {
        float e = __expf(sc[l] - m);
        sc[l] = e;
        s += e;
    }
    #pragma unroll
    for (int o = 16; o > 0; o >>= 1)
        s += __shfl_xor_sync(0xFFFFFFFFu, s, o);
    if (lane == 0) red2[warp] = s;
    __syncthreads();
    if (warp == 0) {
        float x = (lane < 8) ? red2[lane] : 0.f;
        #pragma unroll
        for (int o = 4; o > 0; o >>= 1)
            x += __shfl_xor_sync(0xFFFFFFFFu, x, o);
        if (lane == 0) red2[0] = x;
    }
    __syncthreads();
    const float inv = 1.0f / red2[0];

    // ---- P * V ----
    const int d    = tid & 63;
    const int part = tid >> 6;
    float acc = 0.f;
    for (int l = part; l < n; l += 4) {
        const float* vr;
        if (l == pos) {
            vr = vnew;
        } else {
            int blk = bts[l >> 6];
            vr = vcache + ((bh_base + blk) * BS_ + (l & 63)) * D_;
        }
        acc += sc[l] * vr[d];
    }
    pvb[part][d] = acc;
    __syncthreads();
    if (tid < D_) {
        float o = (pvb[0][tid] + pvb[1][tid]) + (pvb[2][tid] + pvb[3][tid]);
        g_attn[b * E_ + h * D_ + tid] = o * inv;
    }
}

// ---------------------------------------------------------------------------
extern "C" void kernel_launch(void* const* d_in, const int* in_sizes, int n_in,
                              void* d_out, int out_size) {
    const float* hidden = (const float*)d_in[0];
    const float* kcache = (const float*)d_in[1];
    const float* vcache = (const float*)d_in[2];
    const float* wq     = (const float*)d_in[3];
    const float* bq     = (const float*)d_in[4];
    const float* wk     = (const float*)d_in[5];
    const float* bk     = (const float*)d_in[6];
    const float* wv     = (const float*)d_in[7];
    const float* bv     = (const float*)d_in[8];
    const float* wo     = (const float*)d_in[9];
    const float* bo     = (const float*)d_in[10];
    const int*   cpos   = (const int*)d_in[11];
    const int*   btab   = (const int*)d_in[12];
    float* out = (float*)d_out;

    init_kernel<<<(B_ * E_ + 255) / 256, 256>>>(bq, bk, bv, bo, out);

    // QKV fused: 10 n-tiles x 5 k-splits x 3 weights = 150 blocks (one wave)
    qkv_kernel<<<dim3(E_ / GTN, 5, 3), 256>>>(hidden, wq, wk, wv);

    attn_kernel<<<dim3(B_, H_), 256>>>(kcache, vcache, cpos, btab);

    // O-proj: 10 n-tiles x 10 k-splits = 100 blocks
    oproj_kernel<<<dim3(E_ / GTN, 10), 256>>>(wo, out);
}

// round 3
// speedup vs baseline: 1.8839x; 1.0633x over previous
#include <cuda_runtime.h>
#include <cuda_bf16.h>
#include <math.h>
#include <stdint.h>

// Problem constants
#define B_   64
#define E_   1280
#define H_   20
#define D_   64
#define NB_  7
#define BS_  64
#define L_   (NB_*BS_)      // 448
#define SCALING 0.125f      // 64^-0.5

// Scratch (device globals: allocation-free)
__device__ float g_q[B_ * E_];
__device__ float g_k[B_ * E_];
__device__ float g_v[B_ * E_];
__device__ float g_attn[B_ * E_];

// ---------------------------------------------------------------------------
// Init: biases into q/k/v accumulators and bo into d_out
// ---------------------------------------------------------------------------
__global__ void init_kernel(const float* __restrict__ bq, const float* __restrict__ bk,
                            const float* __restrict__ bv, const float* __restrict__ bo,
                            float* __restrict__ out) {
    int i = blockIdx.x * blockDim.x + threadIdx.x;
    if (i < B_ * E_) {
        int j = i % E_;
        g_q[i] = bq[j];
        g_k[i] = bk[j];
        g_v[i] = bv[j];
        out[i] = bo[j];
    }
}

// ---------------------------------------------------------------------------
// tf32 mma.sync m16n8k8 (row.col), fp32 accumulate
// ---------------------------------------------------------------------------
__device__ __forceinline__ void mma_tf32(float* c,
                                         uint32_t a0, uint32_t a1, uint32_t a2, uint32_t a3,
                                         uint32_t b0, uint32_t b1) {
    asm volatile(
        "mma.sync.aligned.m16n8k8.row.col.f32.tf32.tf32.f32 "
        "{%0,%1,%2,%3}, {%4,%5,%6,%7}, {%8,%9}, {%0,%1,%2,%3};"
        : "+f"(c[0]), "+f"(c[1]), "+f"(c[2]), "+f"(c[3])
        : "r"(a0), "r"(a1), "r"(a2), "r"(a3), "r"(b0), "r"(b1));
}

__device__ __forceinline__ void split_tf32(float x, uint32_t& hi, uint32_t& lo) {
    uint32_t xb = __float_as_uint(x);
    hi = xb & 0xFFFFE000u;                       // tf32-representable high part
    lo = __float_as_uint(x - __uint_as_float(hi));
}

// ---------------------------------------------------------------------------
// Tensor-core GEMM core: C[64, Ntile=128] += A[64,K] * W[N,K]^T over [k0,k0+KC)
// 256 threads = 8 warps (4 m-warps x 2 n-warps). 3-term tf32 split => ~fp32.
// ---------------------------------------------------------------------------
#define GTN 128
#define GTK 32

__device__ __forceinline__ void gemm_core(const float* __restrict__ A,
                                          const float* __restrict__ W,
                                          float* __restrict__ out,
                                          int j0, int k0, int KC) {
    __shared__ float As[64][36];     // [m][k], pad 36: frag LDS conflict-free
    __shared__ float Ws[GTN][36];    // [n][k]

    const int t    = threadIdx.x;
    const int warp = t >> 5;
    const int lane = t & 31;
    const int lg   = lane >> 2;      // groupID 0..7
    const int lt   = lane & 3;       // threadID-in-group 0..3

    const int am = (warp & 3) * 16;  // warp m-base (0..48)
    const int bn = (warp >> 2) * 64; // warp n-base within tile (0 or 64)

    float c[8][4] = {};              // 8 n8-tiles x 4 accum

    for (int kt = k0; kt < k0 + KC; kt += GTK) {
        // Load A tile 64x32 (512 float4s, 2 per thread)
        #pragma unroll
        for (int r = 0; r < 2; r++) {
            int f   = t + r * 256;
            int row = f >> 3;
            int q   = f & 7;
            float4 v = *(const float4*)(A + row * E_ + kt + q * 4);
            *(float4*)&As[row][q * 4] = v;
        }
        // Load W tile 128x32 (1024 float4s, 4 per thread)
        #pragma unroll
        for (int r = 0; r < 4; r++) {
            int f   = t + r * 256;
            int row = f >> 3;
            int q   = f & 7;
            float4 v = *(const float4*)(W + (size_t)(j0 + row) * E_ + kt + q * 4);
            *(float4*)&Ws[row][q * 4] = v;
        }
        __syncthreads();

        #pragma unroll
        for (int kk = 0; kk < GTK; kk += 8) {
            // A fragment (m16 x k8), split hi/lo
            uint32_t ah0, al0, ah1, al1, ah2, al2, ah3, al3;
            split_tf32(As[am + lg    ][kk + lt    ], ah0, al0);
            split_tf32(As[am + lg + 8][kk + lt    ], ah1, al1);
            split_tf32(As[am + lg    ][kk + lt + 4], ah2, al2);
            split_tf32(As[am + lg + 8][kk + lt + 4], ah3, al3);

            #pragma unroll
            for (int nt = 0; nt < 8; nt++) {
                uint32_t bh0, bl0, bh1, bl1;
                split_tf32(Ws[bn + nt * 8 + lg][kk + lt    ], bh0, bl0);
                split_tf32(Ws[bn + nt * 8 + lg][kk + lt + 4], bh1, bl1);
                mma_tf32(c[nt], ah0, ah1, ah2, ah3, bh0, bh1);
                mma_tf32(c[nt], ah0, ah1, ah2, ah3, bl0, bl1);
                mma_tf32(c[nt], al0, al1, al2, al3, bh0, bh1);
            }
        }
        __syncthreads();
    }

    // Epilogue: atomicAdd into bias-initialized output
    const int row0 = am + lg;
    #pragma unroll
    for (int nt = 0; nt < 8; nt++) {
        int col = j0 + bn + nt * 8 + 2 * lt;
        atomicAdd(&out[ row0      * E_ + col    ], c[nt][0]);
        atomicAdd(&out[ row0      * E_ + col + 1], c[nt][1]);
        atomicAdd(&out[(row0 + 8) * E_ + col    ], c[nt][2]);
        atomicAdd(&out[(row0 + 8) * E_ + col + 1], c[nt][3]);
    }
}

// QKV fused: grid (10 n-tiles, 5 k-splits, 3 weights), KC=256
__global__ void __launch_bounds__(256) qkv_kernel(const float* __restrict__ hidden,
                                                  const float* __restrict__ wq,
                                                  const float* __restrict__ wk,
                                                  const float* __restrict__ wv) {
    const float* W;
    float* out;
    if (blockIdx.z == 0)      { W = wq; out = g_q; }
    else if (blockIdx.z == 1) { W = wk; out = g_k; }
    else                      { W = wv; out = g_v; }
    gemm_core(hidden, W, out, blockIdx.x * GTN, blockIdx.y * 256, 256);
}

// O-proj: grid (10 n-tiles, 10 k-splits), KC=128
__global__ void __launch_bounds__(256) oproj_kernel(const float* __restrict__ wo,
                                                    float* __restrict__ out) {
    gemm_core(g_attn, wo, out, blockIdx.x * GTN, blockIdx.y * 128, 128);
}

// ---------------------------------------------------------------------------
// Attention: one CTA per (b, h). 256 threads.
// ---------------------------------------------------------------------------
__global__ void attn_kernel(const float* __restrict__ kcache,
                            const float* __restrict__ vcache,
                            const int* __restrict__ cache_position,
                            const int* __restrict__ block_tables) {
    __shared__ float qs[D_];
    __shared__ float sc[L_];
    __shared__ float redbuf[8];
    __shared__ float red2[8];
    __shared__ int   bts[NB_];
    __shared__ float pvb[4][D_];

    const int b = blockIdx.x;
    const int h = blockIdx.y;
    const int tid  = threadIdx.x;
    const int warp = tid >> 5;
    const int lane = tid & 31;

    if (tid < D_)  qs[tid]  = g_q[b * E_ + h * D_ + tid];
    if (tid < NB_) bts[tid] = block_tables[b * NB_ + tid];
    const int pos = cache_position[b];
    const int n   = pos + 1;
    __syncthreads();

    const size_t bh_base = ((size_t)b * H_ + h) * NB_;
    const float* knew = &g_k[b * E_ + h * D_];
    const float* vnew = &g_v[b * E_ + h * D_];

    // ---- scores ----
    for (int l = warp; l < n; l += 8) {
        const float* kr;
        if (l == pos) {
            kr = knew;
        } else {
            int blk = bts[l >> 6];
            kr = kcache + ((bh_base + blk) * BS_ + (l & 63)) * D_;
        }
        float2 kv = ((const float2*)kr)[lane];
        float p = qs[2 * lane] * kv.x + qs[2 * lane + 1] * kv.y;
        #pragma unroll
        for (int o = 16; o > 0; o >>= 1)
            p += __shfl_xor_sync(0xFFFFFFFFu, p, o);
        if (lane == 0) sc[l] = p * SCALING;
    }
    __syncthreads();

    // ---- softmax: max ----
    float m = -1e30f;
    for (int l = tid; l < n; l += 256) m = fmaxf(m, sc[l]);
    #pragma unroll
    for (int o = 16; o > 0; o >>= 1)
        m = fmaxf(m, __shfl_xor_sync(0xFFFFFFFFu, m, o));
    if (lane == 0) redbuf[warp] = m;
    __syncthreads();
    if (warp == 0) {
        float x = (lane < 8) ? redbuf[lane] : -1e30f;
        #pragma unroll
        for (int o = 4; o > 0; o >>= 1)
            x = fmaxf(x, __shfl_xor_sync(0xFFFFFFFFu, x, o));
        if (lane == 0) redbuf[0] = x;
    }
    __syncthreads();
    m = redbuf[0];

    // ---- exp + sum ----
    float s = 0.f;
    for (int l = tid; l < n; l += 256) {
        float e = __expf(sc[l] - m);
        sc[l] = e;
        s += e;
    }
    #pragma unroll
    for (int o = 16; o > 0; o >>= 1)
        s += __shfl_xor_sync(0xFFFFFFFFu, s, o);
    if (lane == 0) red2[warp] = s;
    __syncthreads();
    if (warp == 0) {
        float x = (lane < 8) ? red2[lane] : 0.f;
        #pragma unroll
        for (int o = 4; o > 0; o >>= 1)
            x += __shfl_xor_sync(0xFFFFFFFFu, x, o);
        if (lane == 0) red2[0] = x;
    }
    __syncthreads();
    const float inv = 1.0f / red2[0];

    // ---- P * V ----
    const int d    = tid & 63;
    const int part = tid >> 6;
    float acc = 0.f;
    for (int l = part; l < n; l += 4) {
        const float* vr;
        if (l == pos) {
            vr = vnew;
        } else {
            int blk = bts[l >> 6];
            vr = vcache + ((bh_base + blk) * BS_ + (l & 63)) * D_;
        }
        acc += sc[l] * vr[d];
    }
    pvb[part][d] = acc;
    __syncthreads();
    if (tid < D_) {
        float o = (pvb[0][tid] + pvb[1][tid]) + (pvb[2][tid] + pvb[3][tid]);
        g_attn[b * E_ + h * D_ + tid] = o * inv;
    }
}

// ---------------------------------------------------------------------------
extern "C" void kernel_launch(void* const* d_in, const int* in_sizes, int n_in,
                              void* d_out, int out_size) {
    const float* hidden = (const float*)d_in[0];
    const float* kcache = (const float*)d_in[1];
    const float* vcache = (const float*)d_in[2];
    const float* wq     = (const float*)d_in[3];
    const float* bq     = (const float*)d_in[4];
    const float* wk     = (const float*)d_in[5];
    const float* bk     = (const float*)d_in[6];
    const float* wv     = (const float*)d_in[7];
    const float* bv     = (const float*)d_in[8];
    const float* wo     = (const float*)d_in[9];
    const float* bo     = (const float*)d_in[10];
    const int*   cpos   = (const int*)d_in[11];
    const int*   btab   = (const int*)d_in[12];
    float* out = (float*)d_out;

    init_kernel<<<(B_ * E_ + 255) / 256, 256>>>(bq, bk, bv, bo, out);

    // QKV fused: 10 n-tiles x 5 k-splits x 3 weights = 150 blocks (one wave)
    qkv_kernel<<<dim3(E_ / GTN, 5, 3), 256>>>(hidden, wq, wk, wv);

    attn_kernel<<<dim3(B_, H_), 256>>>(kcache, vcache, cpos, btab);

    // O-proj: 10 n-tiles x 10 k-splits = 100 blocks
    oproj_kernel<<<dim3(E_ / GTN, 10), 256>>>(wo, out);
}

// round 5
// speedup vs baseline: 2.1125x; 1.1213x over previous
#include <cuda_runtime.h>
#include <cuda_bf16.h>
#include <math.h>
#include <stdint.h>

// Problem constants
#define B_   64
#define E_   1280
#define H_   20
#define D_   64
#define NB_  7
#define BS_  64
#define L_   (NB_*BS_)      // 448
#define SCALING 0.125f      // 64^-0.5

// Scratch (device globals: allocation-free)
__device__ float g_q[B_ * E_];
__device__ float g_k[B_ * E_];
__device__ float g_v[B_ * E_];
__device__ float g_attn[B_ * E_];

// ---------------------------------------------------------------------------
// Init: biases into q/k/v accumulators and bo into d_out
// ---------------------------------------------------------------------------
__global__ void init_kernel(const float* __restrict__ bq, const float* __restrict__ bk,
                            const float* __restrict__ bv, const float* __restrict__ bo,
                            float* __restrict__ out) {
    int i = blockIdx.x * blockDim.x + threadIdx.x;
    if (i < B_ * E_) {
        int j = i % E_;
        g_q[i] = bq[j];
        g_k[i] = bk[j];
        g_v[i] = bv[j];
        out[i] = bo[j];
    }
}

// ---------------------------------------------------------------------------
// tf32 mma.sync m16n8k8 (row.col), fp32 accumulate
// ---------------------------------------------------------------------------
__device__ __forceinline__ void mma_tf32(float* c,
                                         uint32_t a0, uint32_t a1, uint32_t a2, uint32_t a3,
                                         uint32_t b0, uint32_t b1) {
    asm volatile(
        "mma.sync.aligned.m16n8k8.row.col.f32.tf32.tf32.f32 "
        "{%0,%1,%2,%3}, {%4,%5,%6,%7}, {%8,%9}, {%0,%1,%2,%3};"
        : "+f"(c[0]), "+f"(c[1]), "+f"(c[2]), "+f"(c[3])
        : "r"(a0), "r"(a1), "r"(a2), "r"(a3), "r"(b0), "r"(b1));
}

__device__ __forceinline__ void split2(float x, uint32_t& hi, uint32_t& lo) {
    uint32_t xb = __float_as_uint(x);
    hi = xb & 0xFFFFE000u;                       // tf32-representable high part
    lo = __float_as_uint(x - __uint_as_float(hi));
}

// ---------------------------------------------------------------------------
// Tensor-core GEMM core, pre-split operands in dynamic smem.
// C[64, Ntile=128] += A[64,K] * W[N,K]^T over [k0,k0+KC)
// 256 threads = 8 warps: 2 m-warps (m32) x 4 n-warps (n32).
// ---------------------------------------------------------------------------
#define GTN 128
#define GTK 32
#define SRS 36                       // smem row stride (words)
#define SMEM_WORDS ((64 + 64 + 128 + 128) * SRS)   // 13824 words = 55296 B

__device__ __forceinline__ void gemm_core(const float* __restrict__ A,
                                          const float* __restrict__ W,
                                          float* __restrict__ out,
                                          int j0, int k0, int KC) {
    extern __shared__ uint32_t smem[];
    uint32_t* As_h = smem;                   // [64][SRS]
    uint32_t* As_l = As_h + 64 * SRS;
    uint32_t* Ws_h = As_l + 64 * SRS;        // [128][SRS]
    uint32_t* Ws_l = Ws_h + 128 * SRS;

    const int t    = threadIdx.x;
    const int warp = t >> 5;
    const int lane = t & 31;
    const int lg   = lane >> 2;      // 0..7
    const int lt   = lane & 3;       // 0..3

    const int am = (warp & 1) * 32;  // warp m-base (0/32)
    const int bn = (warp >> 1) * 32; // warp n-base (0/32/64/96)

    float c[2][4][4] = {};           // [m-frag][n-tile][accum]

    for (int kt = k0; kt < k0 + KC; kt += GTK) {
        // ---- Load + split A tile 64x32 (512 float4s, 2/thread) ----
        #pragma unroll
        for (int r = 0; r < 2; r++) {
            int f   = t + r * 256;
            int row = f >> 3;
            int q   = f & 7;
            float4 v = *(const float4*)(A + row * E_ + kt + q * 4);
            uint32_t h0,l0,h1,l1,h2,l2,h3,l3;
            split2(v.x, h0, l0); split2(v.y, h1, l1);
            split2(v.z, h2, l2); split2(v.w, h3, l3);
            *(uint4*)&As_h[row * SRS + q * 4] = make_uint4(h0, h1, h2, h3);
            *(uint4*)&As_l[row * SRS + q * 4] = make_uint4(l0, l1, l2, l3);
        }
        // ---- Load + split W tile 128x32 (1024 float4s, 4/thread) ----
        #pragma unroll
        for (int r = 0; r < 4; r++) {
            int f   = t + r * 256;
            int row = f >> 3;
            int q   = f & 7;
            float4 v = *(const float4*)(W + (size_t)(j0 + row) * E_ + kt + q * 4);
            uint32_t h0,l0,h1,l1,h2,l2,h3,l3;
            split2(v.x, h0, l0); split2(v.y, h1, l1);
            split2(v.z, h2, l2); split2(v.w, h3, l3);
            *(uint4*)&Ws_h[row * SRS + q * 4] = make_uint4(h0, h1, h2, h3);
            *(uint4*)&Ws_l[row * SRS + q * 4] = make_uint4(l0, l1, l2, l3);
        }
        __syncthreads();

        #pragma unroll
        for (int kk = 0; kk < GTK; kk += 8) {
            uint32_t ah[2][4], al[2][4];
            #pragma unroll
            for (int mi = 0; mi < 2; mi++) {
                int r0 = (am + mi * 16 + lg) * SRS + kk + lt;
                int r1 = (am + mi * 16 + 8 + lg) * SRS + kk + lt;
                ah[mi][0] = As_h[r0];     ah[mi][1] = As_h[r1];
                ah[mi][2] = As_h[r0 + 4]; ah[mi][3] = As_h[r1 + 4];
                al[mi][0] = As_l[r0];     al[mi][1] = As_l[r1];
                al[mi][2] = As_l[r0 + 4]; al[mi][3] = As_l[r1 + 4];
            }
            #pragma unroll
            for (int nt = 0; nt < 4; nt++) {
                int rb = (bn + nt * 8 + lg) * SRS + kk + lt;
                uint32_t bh0 = Ws_h[rb], bh1 = Ws_h[rb + 4];
                uint32_t bl0 = Ws_l[rb], bl1 = Ws_l[rb + 4];
                #pragma unroll
                for (int mi = 0; mi < 2; mi++) {
                    mma_tf32(c[mi][nt], ah[mi][0], ah[mi][1], ah[mi][2], ah[mi][3], bh0, bh1);
                    mma_tf32(c[mi][nt], ah[mi][0], ah[mi][1], ah[mi][2], ah[mi][3], bl0, bl1);
                    mma_tf32(c[mi][nt], al[mi][0], al[mi][1], al[mi][2], al[mi][3], bh0, bh1);
                }
            }
        }
        __syncthreads();
    }

    // Epilogue: atomicAdd into bias-initialized output
    #pragma unroll
    for (int mi = 0; mi < 2; mi++) {
        int row0 = am + mi * 16 + lg;
        #pragma unroll
        for (int nt = 0; nt < 4; nt++) {
            int col = j0 + bn + nt * 8 + 2 * lt;
            atomicAdd(&out[ row0      * E_ + col    ], c[mi][nt][0]);
            atomicAdd(&out[ row0      * E_ + col + 1], c[mi][nt][1]);
            atomicAdd(&out[(row0 + 8) * E_ + col    ], c[mi][nt][2]);
            atomicAdd(&out[(row0 + 8) * E_ + col + 1], c[mi][nt][3]);
        }
    }
}

// QKV fused: grid (10 n-tiles, 10 k-splits, 3 weights), KC=128 -> 300 blocks
__global__ void __launch_bounds__(256) qkv_kernel(const float* __restrict__ hidden,
                                                  const float* __restrict__ wq,
                                                  const float* __restrict__ wk,
                                                  const float* __restrict__ wv) {
    const float* W;
    float* out;
    if (blockIdx.z == 0)      { W = wq; out = g_q; }
    else if (blockIdx.z == 1) { W = wk; out = g_k; }
    else                      { W = wv; out = g_v; }
    gemm_core(hidden, W, out, blockIdx.x * GTN, blockIdx.y * 128, 128);
}

// O-proj: grid (10 n-tiles, 20 k-splits), KC=64 -> 200 blocks
__global__ void __launch_bounds__(256) oproj_kernel(const float* __restrict__ wo,
                                                    float* __restrict__ out) {
    gemm_core(g_attn, wo, out, blockIdx.x * GTN, blockIdx.y * 64, 64);
}

// ---------------------------------------------------------------------------
// Attention: one CTA per (b, h). 256 threads.
// ---------------------------------------------------------------------------
__global__ void attn_kernel(const float* __restrict__ kcache,
                            const float* __restrict__ vcache,
                            const int* __restrict__ cache_position,
                            const int* __restrict__ block_tables) {
    __shared__ float qs[D_];
    __shared__ float sc[L_];
    __shared__ float redbuf[8];
    __shared__ float red2[8];
    __shared__ int   bts[NB_];
    __shared__ float pvb[4][D_];

    const int b = blockIdx.x;
    const int h = blockIdx.y;
    const int tid  = threadIdx.x;
    const int warp = tid >> 5;
    const int lane = tid & 31;

    if (tid < D_)  qs[tid]  = g_q[b * E_ + h * D_ + tid];
    if (tid < NB_) bts[tid] = block_tables[b * NB_ + tid];
    const int pos = cache_position[b];
    const int n   = pos + 1;
    __syncthreads();

    const size_t bh_base = ((size_t)b * H_ + h) * NB_;
    const float* knew = &g_k[b * E_ + h * D_];
    const float* vnew = &g_v[b * E_ + h * D_];

    // ---- scores: 2 rows per warp (16 lanes each), float4 loads ----
    const int half = lane >> 4;      // 0/1
    const int hl   = lane & 15;
    for (int l0 = warp * 2; l0 < n; l0 += 16) {
        int l = l0 + half;
        float p = 0.f;
        if (l < n) {
            const float* kr;
            if (l == pos) {
                kr = knew;
            } else {
                int blk = bts[l >> 6];
                kr = kcache + ((bh_base + blk) * BS_ + (l & 63)) * D_;
            }
            float4 kv = ((const float4*)kr)[hl];
            float4 qv = ((const float4*)qs)[hl];
            p = qv.x * kv.x + qv.y * kv.y + qv.z * kv.z + qv.w * kv.w;
        }
        #pragma unroll
        for (int o = 8; o > 0; o >>= 1)
            p += __shfl_xor_sync(0xFFFFFFFFu, p, o);
        if (hl == 0 && l < n) sc[l] = p * SCALING;
    }
    __syncthreads();

    // ---- softmax: max ----
    float m = -1e30f;
    for (int l = tid; l < n; l += 256) m = fmaxf(m, sc[l]);
    #pragma unroll
    for (int o = 16; o > 0; o >>= 1)
        m = fmaxf(m, __shfl_xor_sync(0xFFFFFFFFu, m, o));
    if (lane == 0) redbuf[warp] = m;
    __syncthreads();
    if (warp == 0) {
        float x = (lane < 8) ? redbuf[lane] : -1e30f;
        #pragma unroll
        for (int o = 4; o > 0; o >>= 1)
            x = fmaxf(x, __shfl_xor_sync(0xFFFFFFFFu, x, o));
        if (lane == 0) redbuf[0] = x;
    }
    __syncthreads();
    m = redbuf[0];

    // ---- exp + sum ----
    float s = 0.f;
    for (int l = tid; l < n; l += 256) {
        float e = __expf(sc[l] - m);
        sc[l] = e;
        s += e;
    }
    #pragma unroll
    for (int o = 16; o > 0; o >>= 1)
        s += __shfl_xor_sync(0xFFFFFFFFu, s, o);
    if (lane == 0) red2[warp] = s;
    __syncthreads();
    if (warp == 0) {
        float x = (lane < 8) ? red2[lane] : 0.f;
        #pragma unroll
        for (int o = 4; o > 0; o >>= 1)
            x += __shfl_xor_sync(0xFFFFFFFFu, x, o);
        if (lane == 0) red2[0] = x;
    }
    __syncthreads();
    const float inv = 1.0f / red2[0];

    // ---- P * V ----
    const int d    = tid & 63;
    const int part = tid >> 6;
    float acc = 0.f;
    #pragma unroll 2
    for (int l = part; l < n; l += 4) {
        const float* vr;
        if (l == pos) {
            vr = vnew;
        } else {
            int blk = bts[l >> 6];
            vr = vcache + ((bh_base + blk) * BS_ + (l & 63)) * D_;
        }
        acc += sc[l] * vr[d];
    }
    pvb[part][d] = acc;
    __syncthreads();
    if (tid < D_) {
        float o = (pvb[0][tid] + pvb[1][tid]) + (pvb[2][tid] + pvb[3][tid]);
        g_attn[b * E_ + h * D_ + tid] = o * inv;
    }
}

// ---------------------------------------------------------------------------
extern "C" void kernel_launch(void* const* d_in, const int* in_sizes, int n_in,
                              void* d_out, int out_size) {
    const float* hidden = (const float*)d_in[0];
    const float* kcache = (const float*)d_in[1];
    const float* vcache = (const float*)d_in[2];
    const float* wq     = (const float*)d_in[3];
    const float* bq     = (const float*)d_in[4];
    const float* wk     = (const float*)d_in[5];
    const float* bk     = (const float*)d_in[6];
    const float* wv     = (const float*)d_in[7];
    const float* bv     = (const float*)d_in[8];
    const float* wo     = (const float*)d_in[9];
    const float* bo     = (const float*)d_in[10];
    const int*   cpos   = (const int*)d_in[11];
    const int*   btab   = (const int*)d_in[12];
    float* out = (float*)d_out;

    const int smem_bytes = SMEM_WORDS * 4;   // 55296
    cudaFuncSetAttribute(qkv_kernel,  cudaFuncAttributeMaxDynamicSharedMemorySize, smem_bytes);
    cudaFuncSetAttribute(oproj_kernel, cudaFuncAttributeMaxDynamicSharedMemorySize, smem_bytes);

    init_kernel<<<(B_ * E_ + 255) / 256, 256>>>(bq, bk, bv, bo, out);

    // QKV fused: 10 n-tiles x 10 k-splits x 3 weights = 300 blocks (2 CTAs/SM)
    qkv_kernel<<<dim3(E_ / GTN, 10, 3), 256, smem_bytes>>>(hidden, wq, wk, wv);

    attn_kernel<<<dim3(B_, H_), 256>>>(kcache, vcache, cpos, btab);

    // O-proj: 10 n-tiles x 20 k-splits = 200 blocks
    oproj_kernel<<<dim3(E_ / GTN, 20), 256, smem_bytes>>>(wo, out);
}

// round 7
// speedup vs baseline: 3.1443x; 1.4884x over previous
#include <cuda_runtime.h>
#include <cuda_bf16.h>
#include <math.h>
#include <stdint.h>

// Problem constants
#define B_   64
#define E_   1280
#define H_   20
#define D_   64
#define NB_  7
#define BS_  64
#define L_   (NB_*BS_)      // 448
#define SCALING 0.125f      // 64^-0.5

// Scratch (device globals: allocation-free). 16B-aligned for float4 access.
__device__ __align__(16) float g_q[B_ * E_];
__device__ __align__(16) float g_k[B_ * E_];
__device__ __align__(16) float g_v[B_ * E_];
__device__ __align__(16) float g_attn[B_ * E_];

// ---------------------------------------------------------------------------
// Init: biases into q/k/v accumulators and bo into d_out
// ---------------------------------------------------------------------------
__global__ void init_kernel(const float* __restrict__ bq, const float* __restrict__ bk,
                            const float* __restrict__ bv, const float* __restrict__ bo,
                            float* __restrict__ out) {
    int i = blockIdx.x * blockDim.x + threadIdx.x;
    if (i < B_ * E_) {
        int j = i % E_;
        g_q[i] = bq[j];
        g_k[i] = bk[j];
        g_v[i] = bv[j];
        out[i] = bo[j];
    }
}

// ---------------------------------------------------------------------------
// bf16 mma.sync m16n8k16 (row.col), fp32 accumulate
// ---------------------------------------------------------------------------
__device__ __forceinline__ void mma_bf16(float* c,
                                         uint32_t a0, uint32_t a1, uint32_t a2, uint32_t a3,
                                         uint32_t b0, uint32_t b1) {
    asm volatile(
        "mma.sync.aligned.m16n8k16.row.col.f32.bf16.bf16.f32 "
        "{%0,%1,%2,%3}, {%4,%5,%6,%7}, {%8,%9}, {%0,%1,%2,%3};"
        : "+f"(c[0]), "+f"(c[1]), "+f"(c[2]), "+f"(c[3])
        : "r"(a0), "r"(a1), "r"(a2), "r"(a3), "r"(b0), "r"(b1));
}

// Split float4 into packed-bf16x2 hi/lo planes.
// hi = truncate-to-bf16 (residual exact in fp32), lo = rn_bf16(residual).
__device__ __forceinline__ void splitpack(float4 v, uint32_t& h0, uint32_t& h1,
                                          uint32_t& l0, uint32_t& l1) {
    uint32_t bx = __float_as_uint(v.x), by = __float_as_uint(v.y);
    uint32_t bz = __float_as_uint(v.z), bw = __float_as_uint(v.w);
    uint32_t hx = bx & 0xFFFF0000u, hy = by & 0xFFFF0000u;
    uint32_t hz = bz & 0xFFFF0000u, hw = bw & 0xFFFF0000u;
    h0 = (bx >> 16) | hy;            // low half = x (even k), high half = y
    h1 = (bz >> 16) | hw;
    float rx = v.x - __uint_as_float(hx);
    float ry = v.y - __uint_as_float(hy);
    float rz = v.z - __uint_as_float(hz);
    float rw = v.w - __uint_as_float(hw);
    __nv_bfloat162 p0 = __floats2bfloat162_rn(rx, ry);
    __nv_bfloat162 p1 = __floats2bfloat162_rn(rz, rw);
    l0 = *(uint32_t*)&p0;
    l1 = *(uint32_t*)&p1;
}

// ---------------------------------------------------------------------------
// Tensor-core GEMM core (bf16 3-term, double-buffered smem).
// C[64, Ntile=128] += A[64,K] * W[N,K]^T over [k0,k0+KC)
// 256 threads = 8 warps: 2 m-warps (m32) x 4 n-warps (n32).
// ---------------------------------------------------------------------------
#define GTN 128
#define GTK 32
#define PLW 20                    // plane row stride (words); conflict-free frags
#define APW (64 * PLW)
#define WPW (128 * PLW)
#define BUFW (2 * APW + 2 * WPW)  // Ah, Al, Wh, Wl = 7680 words
#define SMEM_WORDS (2 * BUFW)     // 15360 words = 61440 B

__device__ __forceinline__ void gemm_core(const float* __restrict__ A,
                                          const float* __restrict__ W,
                                          float* __restrict__ out,
                                          int j0, int k0, int KC) {
    extern __shared__ __align__(16) uint32_t smem[];
    const int t    = threadIdx.x;
    const int warp = t >> 5;
    const int lane = t & 31;
    const int lg   = lane >> 2;
    const int lt   = lane & 3;
    const int am   = (warp & 1) * 32;
    const int bn   = (warp >> 1) * 32;

    float c[2][4][4] = {};
    float4 ra[2], rw[4];

    const int lrowA = t >> 3;          // 0..31 (+32 with r)
    const int lq    = t & 7;

    // -- stage tile kt into registers --
    auto load_tile = [&](int kt) {
        #pragma unroll
        for (int r = 0; r < 2; r++)
            ra[r] = *(const float4*)(A + (lrowA + r * 32) * E_ + kt + lq * 4);
        #pragma unroll
        for (int r = 0; r < 4; r++)
            rw[r] = *(const float4*)(W + (size_t)(j0 + lrowA + r * 32) * E_ + kt + lq * 4);
    };
    // -- split + store staged regs into buffer --
    auto store_tile = [&](int buf) {
        uint32_t* Ah = smem + buf * BUFW;
        uint32_t* Al = Ah + APW;
        uint32_t* Wh = Al + APW;
        uint32_t* Wl = Wh + WPW;
        #pragma unroll
        for (int r = 0; r < 2; r++) {
            uint32_t h0, h1, l0, l1;
            splitpack(ra[r], h0, h1, l0, l1);
            int base = (lrowA + r * 32) * PLW + lq * 2;
            Ah[base] = h0; Ah[base + 1] = h1;
            Al[base] = l0; Al[base + 1] = l1;
        }
        #pragma unroll
        for (int r = 0; r < 4; r++) {
            uint32_t h0, h1, l0, l1;
            splitpack(rw[r], h0, h1, l0, l1);
            int base = (lrowA + r * 32) * PLW + lq * 2;
            Wh[base] = h0; Wh[base + 1] = h1;
            Wl[base] = l0; Wl[base + 1] = l1;
        }
    };
    // -- mma over one buffer --
    auto mma_tiles = [&](int buf) {
        uint32_t* Ah = smem + buf * BUFW;
        uint32_t* Al = Ah + APW;
        uint32_t* Wh = Al + APW;
        uint32_t* Wl = Wh + WPW;
        #pragma unroll
        for (int ks = 0; ks < GTK / 16; ks++) {
            int kw = ks * 8;
            uint32_t ah[2][4], al[2][4];
            #pragma unroll
            for (int mi = 0; mi < 2; mi++) {
                int r0 = (am + mi * 16 + lg) * PLW + kw + lt;
                int r1 = r0 + 8 * PLW;
                ah[mi][0] = Ah[r0];     ah[mi][1] = Ah[r1];
                ah[mi][2] = Ah[r0 + 4]; ah[mi][3] = Ah[r1 + 4];
                al[mi][0] = Al[r0];     al[mi][1] = Al[r1];
                al[mi][2] = Al[r0 + 4]; al[mi][3] = Al[r1 + 4];
            }
            #pragma unroll
            for (int nt = 0; nt < 4; nt++) {
                int rb = (bn + nt * 8 + lg) * PLW + kw + lt;
                uint32_t bh0 = Wh[rb], bh1 = Wh[rb + 4];
                uint32_t bl0 = Wl[rb], bl1 = Wl[rb + 4];
                #pragma unroll
                for (int mi = 0; mi < 2; mi++) {
                    mma_bf16(c[mi][nt], ah[mi][0], ah[mi][1], ah[mi][2], ah[mi][3], bh0, bh1);
                    mma_bf16(c[mi][nt], ah[mi][0], ah[mi][1], ah[mi][2], ah[mi][3], bl0, bl1);
                    mma_bf16(c[mi][nt], al[mi][0], al[mi][1], al[mi][2], al[mi][3], bh0, bh1);
                }
            }
        }
    };

    const int ntiles = KC / GTK;
    load_tile(k0);
    store_tile(0);
    __syncthreads();
    for (int it = 0; it < ntiles; it++) {
        if (it + 1 < ntiles) load_tile(k0 + (it + 1) * GTK);
        mma_tiles(it & 1);
        if (it + 1 < ntiles) {
            store_tile((it + 1) & 1);
            __syncthreads();
        }
    }

    // Epilogue: atomicAdd into bias-initialized output
    #pragma unroll
    for (int mi = 0; mi < 2; mi++) {
        int row0 = am + mi * 16 + lg;
        #pragma unroll
        for (int nt = 0; nt < 4; nt++) {
            int col = j0 + bn + nt * 8 + 2 * lt;
            atomicAdd(&out[ row0      * E_ + col    ], c[mi][nt][0]);
            atomicAdd(&out[ row0      * E_ + col + 1], c[mi][nt][1]);
            atomicAdd(&out[(row0 + 8) * E_ + col    ], c[mi][nt][2]);
            atomicAdd(&out[(row0 + 8) * E_ + col + 1], c[mi][nt][3]);
        }
    }
}

// QKV fused: grid (10 n-tiles, 10 k-splits, 3 weights), KC=128 -> 300 blocks
__global__ void __launch_bounds__(256) qkv_kernel(const float* __restrict__ hidden,
                                                  const float* __restrict__ wq,
                                                  const float* __restrict__ wk,
                                                  const float* __restrict__ wv) {
    const float* W;
    float* out;
    if (blockIdx.z == 0)      { W = wq; out = g_q; }
    else if (blockIdx.z == 1) { W = wk; out = g_k; }
    else                      { W = wv; out = g_v; }
    gemm_core(hidden, W, out, blockIdx.x * GTN, blockIdx.y * 128, 128);
}

// O-proj: grid (10 n-tiles, 20 k-splits), KC=64 -> 200 blocks
__global__ void __launch_bounds__(256) oproj_kernel(const float* __restrict__ wo,
                                                    float* __restrict__ out) {
    gemm_core(g_attn, wo, out, blockIdx.x * GTN, blockIdx.y * 64, 64);
}

// ---------------------------------------------------------------------------
// Attention: one CTA per (b, h). 256 threads.
// ---------------------------------------------------------------------------
__global__ void attn_kernel(const float* __restrict__ kcache,
                            const float* __restrict__ vcache,
                            const int* __restrict__ cache_position,
                            const int* __restrict__ block_tables) {
    __shared__ __align__(16) float qs[D_];
    __shared__ __align__(16) float sc[L_];
    __shared__ __align__(16) float pvb[16][D_];
    __shared__ float redbuf[8];
    __shared__ float red2[8];
    __shared__ int   bts[NB_];

    const int b = blockIdx.x;
    const int h = blockIdx.y;
    const int tid  = threadIdx.x;
    const int warp = tid >> 5;
    const int lane = tid & 31;

    if (tid < D_)  qs[tid]  = g_q[b * E_ + h * D_ + tid];
    if (tid < NB_) bts[tid] = block_tables[b * NB_ + tid];
    const int pos = cache_position[b];
    const int n   = pos + 1;
    __syncthreads();

    const size_t bh_base = ((size_t)b * H_ + h) * NB_;
    const float* knew = &g_k[b * E_ + h * D_];
    const float* vnew = &g_v[b * E_ + h * D_];

    // ---- scores: 2 rows per warp (16 lanes each), float4 loads ----
    const int half = lane >> 4;
    const int hl   = lane & 15;
    for (int l0 = warp * 2; l0 < n; l0 += 16) {
        int l = l0 + half;
        float p = 0.f;
        if (l < n) {
            const float* kr;
            if (l == pos) {
                kr = knew;
            } else {
                int blk = bts[l >> 6];
                kr = kcache + ((bh_base + blk) * BS_ + (l & 63)) * D_;
            }
            float4 kv = ((const float4*)kr)[hl];
            float4 qv = ((const float4*)qs)[hl];
            p = qv.x * kv.x + qv.y * kv.y + qv.z * kv.z + qv.w * kv.w;
        }
        #pragma unroll
        for (int o = 8; o > 0; o >>= 1)
            p += __shfl_xor_sync(0xFFFFFFFFu, p, o);
        if (hl == 0 && l < n) sc[l] = p * SCALING;
    }
    __syncthreads();

    // ---- softmax: max ----
    float m = -1e30f;
    for (int l = tid; l < n; l += 256) m = fmaxf(m, sc[l]);
    #pragma unroll
    for (int o = 16; o > 0; o >>= 1)
        m = fmaxf(m, __shfl_xor_sync(0xFFFFFFFFu, m, o));
    if (lane == 0) redbuf[warp] = m;
    __syncthreads();
    if (warp == 0) {
        float x = (lane < 8) ? redbuf[lane] : -1e30f;
        #pragma unroll
        for (int o = 4; o > 0; o >>= 1)
            x = fmaxf(x, __shfl_xor_sync(0xFFFFFFFFu, x, o));
        if (lane == 0) redbuf[0] = x;
    }
    __syncthreads();
    m = redbuf[0];

    // ---- exp + sum ----
    float s = 0.f;
    for (int l = tid; l < n; l += 256) {
        float e = __expf(sc[l] - m);
        sc[l] = e;
        s += e;
    }
    #pragma unroll
    for (int o = 16; o > 0; o >>= 1)
        s += __shfl_xor_sync(0xFFFFFFFFu, s, o);
    if (lane == 0) red2[warp] = s;
    __syncthreads();
    if (warp == 0) {
        float x = (lane < 8) ? red2[lane] : 0.f;
        #pragma unroll
        for (int o = 4; o > 0; o >>= 1)
            x += __shfl_xor_sync(0xFFFFFFFFu, x, o);
        if (lane == 0) red2[0] = x;
    }
    __syncthreads();
    const float inv = 1.0f / red2[0];

    // ---- P * V: 16 l-partitions x 16 d-quads, float4 loads ----
    const int dq   = tid & 15;
    const int part = tid >> 4;
    float4 acc = make_float4(0.f, 0.f, 0.f, 0.f);
    #pragma unroll 2
    for (int l = part; l < n; l += 16) {
        const float* vr;
        if (l == pos) {
            vr = vnew;
        } else {
            int blk = bts[l >> 6];
            vr = vcache + ((bh_base + blk) * BS_ + (l & 63)) * D_;
        }
        float4 v = ((const float4*)vr)[dq];
        float p = sc[l];
        acc.x += p * v.x; acc.y += p * v.y; acc.z += p * v.z; acc.w += p * v.w;
    }
    *(float4*)&pvb[part][dq * 4] = acc;
    __syncthreads();
    if (tid < D_) {
        float s2 = 0.f;
        #pragma unroll
        for (int p = 0; p < 16; p++) s2 += pvb[p][tid];
        g_attn[b * E_ + h * D_ + tid] = s2 * inv;
    }
}

// ---------------------------------------------------------------------------
extern "C" void kernel_launch(void* const* d_in, const int* in_sizes, int n_in,
                              void* d_out, int out_size) {
    const float* hidden = (const float*)d_in[0];
    const float* kcache = (const float*)d_in[1];
    const float* vcache = (const float*)d_in[2];
    const float* wq     = (const float*)d_in[3];
    const float* bq     = (const float*)d_in[4];
    const float* wk     = (const float*)d_in[5];
    const float* bk     = (const float*)d_in[6];
    const float* wv     = (const float*)d_in[7];
    const float* bv     = (const float*)d_in[8];
    const float* wo     = (const float*)d_in[9];
    const float* bo     = (const float*)d_in[10];
    const int*   cpos   = (const int*)d_in[11];
    const int*   btab   = (const int*)d_in[12];
    float* out = (float*)d_out;

    const int smem_bytes = SMEM_WORDS * 4;   // 61440
    cudaFuncSetAttribute(qkv_kernel,   cudaFuncAttributeMaxDynamicSharedMemorySize, smem_bytes);
    cudaFuncSetAttribute(oproj_kernel, cudaFuncAttributeMaxDynamicSharedMemorySize, smem_bytes);

    init_kernel<<<(B_ * E_ + 255) / 256, 256>>>(bq, bk, bv, bo, out);

    // QKV fused: 10 n-tiles x 10 k-splits x 3 weights = 300 blocks (2 CTAs/SM)
    qkv_kernel<<<dim3(E_ / GTN, 10, 3), 256, smem_bytes>>>(hidden, wq, wk, wv);

    attn_kernel<<<dim3(B_, H_), 256>>>(kcache, vcache, cpos, btab);

    // O-proj: 10 n-tiles x 20 k-splits = 200 blocks
    oproj_kernel<<<dim3(E_ / GTN, 20), 256, smem_bytes>>>(wo, out);
}